// round 4
// baseline (speedup 1.0000x reference)
#include <cuda_runtime.h>

// Problem shape (fixed by the dataset)
#define TT 4096
#define NB 16
#define CC 512
#define NC (NB * CC)            // 8192 columns
#define CHUNK 64
#define NCHUNKS (TT / CHUNK)    // 64
#define NGRP (NC / 256)         // 32 column groups of 256
#define NBLK (NCHUNKS * NGRP)   // 2048 blocks
#define TOTAL (TT * NC)         // 33,554,432 floats for new_x

// Static scratch (no allocations allowed)
__device__ float g_incl[NCHUNKS * NC];   // 2 MB: per-(chunk,col) INCLUSIVE prefixes
__device__ int   g_flag[NBLK];           // "inclusive prefix published" flags
__device__ float g_rcp[TT * NB];         // 256 KB: 1/(t+1+len_n), layout [t][n]

// k0: reciprocal table + flag reset (flags must reset on every graph replay).
__global__ void k0_prep(const int* __restrict__ cached_len) {
    int idx = blockIdx.x * blockDim.x + threadIdx.x;
    if (idx < NBLK) g_flag[idx] = 0;
    if (idx >= TT * NB) return;
    int n = idx & (NB - 1);
    int t = idx >> 4;
    g_rcp[idx] = 1.0f / ((float)(t + 1) + (float)cached_len[n]);
}

// Single-pass scan, register-resident tile, tail-chase decoupled lookback.
// Block = (chunk, column-group). Each thread owns one column for 64 steps.
// bid = chunk*NGRP + g: all predecessors have lower bid (in-order dispatch).
__global__ void __launch_bounds__(256, 2)
k_main(const float* __restrict__ x,
       const int* __restrict__ cached_len,
       const float* __restrict__ cached_avg,
       float* __restrict__ out, int extras) {
    int bid = blockIdx.x;
    int chunk = bid >> 5;                 // / NGRP
    int g = bid & (NGRP - 1);
    int tid = threadIdx.x;
    int nc = g * 256 + tid;
    int n = nc >> 9;                      // c fastest, C=512

    // ── Phase 1: stream my tile into registers, compute column sum ──
    const float* px = x + (size_t)chunk * CHUNK * NC + nc;
    float v[CHUNK];
#pragma unroll
    for (int i = 0; i < CHUNK; i++) v[i] = px[(size_t)i * NC];
    float s = 0.0f;
#pragma unroll
    for (int i = 0; i < CHUNK; i++) s += v[i];

    // ── Phase 2: tail-chase lookback ──
    float pin;
    if (chunk == 0) {
        pin = cached_avg[nc] * (float)cached_len[n];
    } else {
        if (tid == 0) {
            volatile int* f = &g_flag[bid - NGRP];
            while (*f == 0) __nanosleep(64);
        }
        __syncthreads();
        __threadfence();
        pin = g_incl[(chunk - 1) * NC + nc];
    }
    if (chunk < NCHUNKS - 1) {            // last chunk has no consumer
        g_incl[chunk * NC + nc] = pin + s;
        __threadfence();
        __syncthreads();
        if (tid == 0) g_flag[bid] = 1;
    }

    // ── Phase 3: rescan registers, scale, stream out ──
    const float* pr = g_rcp + (size_t)chunk * CHUNK * NB + n;   // warp-uniform
    float*       po = out   + (size_t)chunk * CHUNK * NC + nc;
    float run = pin;
    float last = 0.0f;
#pragma unroll
    for (int i = 0; i < CHUNK; i++) {
        run += v[i];
        last = run * pr[(size_t)i * NB];
        po[(size_t)i * NC] = last;
    }

    if (extras) {
        // Tuple order: [new_x | new_cached_len (as float) | new_cached_avg]
        if (chunk == NCHUNKS - 1) out[TOTAL + NB + nc] = last;   // new_x[T-1]
        if (bid == 0 && tid < NB) out[TOTAL + tid] = (float)(cached_len[tid] + TT);
    }
}

extern "C" void kernel_launch(void* const* d_in, const int* in_sizes, int n_in,
                              void* d_out, int out_size) {
    const float* x          = (const float*)d_in[0];   // (T, N, C)
    const int*   cached_len = (const int*)d_in[1];     // (N,)
    const float* cached_avg = (const float*)d_in[2];   // (N, C)
    float* out = (float*)d_out;

    int extras = (out_size >= TOTAL + NB + NC) ? 1 : 0;

    k0_prep<<<(TT * NB + 255) / 256, 256>>>(cached_len);
    k_main<<<NBLK, 256>>>(x, cached_len, cached_avg, out, extras);
}

// round 5
// speedup vs baseline: 1.0921x; 1.0921x over previous
#include <cuda_runtime.h>

// Problem shape (fixed by the dataset)
#define TT 4096
#define NB 16
#define CC 512
#define NC (NB * CC)            // 8192 columns
#define CHUNK 64
#define NCHUNKS (TT / CHUNK)    // 64
#define NGRP (NC / 256)         // 32 column groups of 256
#define NBLK (NCHUNKS * NGRP)   // 2048 blocks
#define TOTAL (TT * NC)         // 33,554,432 floats for new_x

// Static scratch. g_pub[chunk*NC+nc] = {hi32: valid tag, lo32: float chunk-sum}.
// A single aligned 8B store is atomic => word is self-validating, no fences needed.
__device__ unsigned long long g_pub[NCHUNKS * NC];   // 4 MB
__device__ float g_rcp[TT * NB];                     // 256 KB: 1/(t+1+len_n), [t][n]

// k0: zero tags (must reset every graph replay) + reciprocal table.
__global__ void k0_prep(const int* __restrict__ cached_len) {
    int idx = blockIdx.x * blockDim.x + threadIdx.x;
    if (idx < NCHUNKS * NC) g_pub[idx] = 0ull;
    if (idx < TT * NB) {
        int n = idx & (NB - 1);
        int t = idx >> 4;
        g_rcp[idx] = 1.0f / ((float)(t + 1) + (float)cached_len[n]);
    }
}

// Single-pass scan: register tile + chain-free per-word aggregate lookback.
// Block = (chunk, column-group); each thread owns one column for 64 steps and
// is fully independent (no __syncthreads / __threadfence anywhere).
__global__ void __launch_bounds__(256, 2)
k_main(const float* __restrict__ x,
       const int* __restrict__ cached_len,
       const float* __restrict__ cached_avg,
       float* __restrict__ out, int extras) {
    int bid = blockIdx.x;
    int chunk = bid >> 5;                 // / NGRP  (chunk-major: predecessors have lower bid)
    int g = bid & (NGRP - 1);
    int tid = threadIdx.x;
    int nc = g * 256 + tid;
    int n = nc >> 9;                      // c fastest, C=512

    // ── Phase 1: stream my tile into registers, compute column sum ──
    const float* px = x + (size_t)chunk * CHUNK * NC + nc;
    float v[CHUNK];
#pragma unroll
    for (int i = 0; i < CHUNK; i++) v[i] = px[(size_t)i * NC];
    float s = 0.0f;
#pragma unroll
    for (int i = 0; i < CHUNK; i++) s += v[i];

    // ── Publish my aggregate immediately (before any waiting) ──
    if (chunk < NCHUNKS - 1) {
        unsigned long long w = (1ull << 32) | (unsigned long long)__float_as_uint(s);
        __stcg(&g_pub[chunk * NC + nc], w);
    }

    // ── Phase 2: sum predecessor aggregates (self-validating words, L2) ──
    float pin = cached_avg[nc] * (float)cached_len[n];
    if (chunk > 0) {
        const unsigned long long* pp = &g_pub[nc];
        unsigned long long pend = (1ull << chunk) - 1ull;   // chunk <= 63
        // Optimistic batched sweep: independent ldcg loads, high MLP.
#pragma unroll 4
        for (int ch = 0; ch < chunk; ch++) {
            unsigned long long w = __ldcg(pp + (size_t)ch * NC);
            if (w >> 32) { pin += __uint_as_float((unsigned)w); pend &= ~(1ull << ch); }
        }
        // Stragglers: backoff-polled, only missing words.
        while (pend) {
            __nanosleep(128);
            unsigned long long m = pend;
            while (m) {
                int ch = __ffsll((long long)m) - 1;
                m &= m - 1;
                unsigned long long w = __ldcg(pp + (size_t)ch * NC);
                if (w >> 32) { pin += __uint_as_float((unsigned)w); pend &= ~(1ull << ch); }
            }
        }
    }

    // ── Phase 3: rescan registers, scale by rcp, stream out ──
    const float* pr = g_rcp + (size_t)chunk * CHUNK * NB + n;   // warp-uniform, L1-hot
    float*       po = out   + (size_t)chunk * CHUNK * NC + nc;
    float run = pin;
    float last = 0.0f;
#pragma unroll
    for (int i = 0; i < CHUNK; i++) {
        run += v[i];
        last = run * pr[(size_t)i * NB];
        po[(size_t)i * NC] = last;
    }

    if (extras) {
        // Tuple order: [new_x | new_cached_len (as float) | new_cached_avg]
        if (chunk == NCHUNKS - 1) out[TOTAL + NB + nc] = last;   // new_x[T-1]
        if (bid == 0 && tid < NB) out[TOTAL + tid] = (float)(cached_len[tid] + TT);
    }
}

extern "C" void kernel_launch(void* const* d_in, const int* in_sizes, int n_in,
                              void* d_out, int out_size) {
    const float* x          = (const float*)d_in[0];   // (T, N, C)
    const int*   cached_len = (const int*)d_in[1];     // (N,)
    const float* cached_avg = (const float*)d_in[2];   // (N, C)
    float* out = (float*)d_out;

    int extras = (out_size >= TOTAL + NB + NC) ? 1 : 0;

    k0_prep<<<(NCHUNKS * NC + 255) / 256, 256>>>(cached_len);
    k_main<<<NBLK, 256>>>(x, cached_len, cached_avg, out, extras);
}

// round 6
// speedup vs baseline: 1.2724x; 1.1650x over previous
#include <cuda_runtime.h>

// Problem shape (fixed by the dataset)
#define TT 4096
#define NB 16
#define CC 512
#define NC (NB * CC)            // 8192 columns
#define NC4 (NC / 4)            // 2048 float4 columns
#define TOTAL (TT * NC)         // 33,554,432 floats for new_x

#define NSEG 4
#define SEG_T (TT / NSEG)       // 1024 rows/segment = 32 MB (L2-resident)
#define CHUNK 16                // rows per thread
#define CPS (SEG_T / CHUNK)     // 64 chunks per segment
#define NCH (TT / CHUNK)        // 256 chunks total
#define SEG_BLOCKS ((CPS * NC4) / 256)   // 512 blocks per segment role
#define RCP_BLOCKS ((TT * NB) / 256)     // 256

// Static scratch (no allocations allowed; all fully rewritten every replay)
__device__ float4 g_agg[NCH * NC4];    // 8 MB: per-(chunk, col4) sums
__device__ float4 g_base[NCH * NC4];   // 8 MB: exclusive bases (seeded)
__device__ float4 g_carry[NC4];        // 32 KB: carry across segments
__device__ float  g_rcp[TT * NB];      // 256 KB: 1/(t+1+len_n), [t][n]

__device__ __forceinline__ void sum_chunk(const float4* __restrict__ x4,
                                          int gc, int nc4) {
    const float4* p = x4 + (size_t)gc * CHUNK * NC4 + nc4;
    float4 s = make_float4(0.f, 0.f, 0.f, 0.f);
#pragma unroll
    for (int i = 0; i < CHUNK; i++) {
        float4 v = p[(size_t)i * NC4];
        s.x += v.x; s.y += v.y; s.z += v.z; s.w += v.w;
    }
    g_agg[gc * NC4 + nc4] = s;
}

// kA: segment-0 partial sums + reciprocal table (role split by blockIdx).
__global__ void __launch_bounds__(256)
kA(const float4* __restrict__ x4, const int* __restrict__ cached_len) {
    int bid = blockIdx.x, tid = threadIdx.x;
    if (bid < SEG_BLOCKS) {
        int idx = bid * 256 + tid;
        sum_chunk(x4, idx >> 11, idx & (NC4 - 1));     // gc = chunk-local (seg 0)
    } else {
        int idx = (bid - SEG_BLOCKS) * 256 + tid;      // 0 .. TT*NB-1
        int n = idx & (NB - 1);
        int t = idx >> 4;
        g_rcp[idx] = 1.0f / ((float)(t + 1) + (float)cached_len[n]);
    }
}

// kscan(s): per-col4 exclusive scan over this segment's 64 chunk sums.
// 2048 threads; all traffic L2-resident; loads are independent (unrolled).
__global__ void __launch_bounds__(256)
kscan(const int* __restrict__ cached_len, const float4* __restrict__ avg4, int s) {
    int col4 = blockIdx.x * 256 + threadIdx.x;         // 0 .. NC4-1
    float4 c;
    if (s == 0) {
        float lenf = (float)cached_len[col4 >> 7];
        c = avg4[col4];
        c.x *= lenf; c.y *= lenf; c.z *= lenf; c.w *= lenf;
    } else {
        c = g_carry[col4];
    }
#pragma unroll
    for (int j = 0; j < CPS; j++) {
        int gc = s * CPS + j;
        float4 a = g_agg[gc * NC4 + col4];
        g_base[gc * NC4 + col4] = c;
        c.x += a.x; c.y += a.y; c.z += a.z; c.w += a.w;
    }
    g_carry[col4] = c;
}

// kC(s): fused — low blocks: final scan of segment s (x[s] is L2-hot from the
// previous launch); high blocks: partial sums of segment s+1 (DRAM streaming,
// overlapped). Independent roles, stream-ordered deps only.
__global__ void __launch_bounds__(256)
kC(const float4* __restrict__ x4, const int* __restrict__ cached_len,
   float4* __restrict__ out4, int s, int extras) {
    int bid = blockIdx.x, tid = threadIdx.x;
    if (bid >= SEG_BLOCKS) {                            // k1 role: segment s+1
        int idx = (bid - SEG_BLOCKS) * 256 + tid;
        sum_chunk(x4, (s + 1) * CPS + (idx >> 11), idx & (NC4 - 1));
        return;
    }
    // k2 role: segment s
    int idx = bid * 256 + tid;
    int nc4 = idx & (NC4 - 1);
    int gc = s * CPS + (idx >> 11);
    int n = nc4 >> 7;                                   // (nc4*4)/512, warp-uniform

    float4 run = g_base[gc * NC4 + nc4];
    const float4* px = x4   + (size_t)gc * CHUNK * NC4 + nc4;
    float4*       po = out4 + (size_t)gc * CHUNK * NC4 + nc4;
    const float*  pr = g_rcp + (size_t)gc * CHUNK * NB + n;

    float4 last = make_float4(0.f, 0.f, 0.f, 0.f);
#pragma unroll
    for (int i = 0; i < CHUNK; i++) {
        float4 v = px[(size_t)i * NC4];
        run.x += v.x; run.y += v.y; run.z += v.z; run.w += v.w;
        float r = pr[(size_t)i * NB];
        last.x = run.x * r; last.y = run.y * r;
        last.z = run.z * r; last.w = run.w * r;
        po[(size_t)i * NC4] = last;
    }

    if (extras && s == NSEG - 1) {
        // Tuple order: [new_x | new_cached_len (as float) | new_cached_avg]
        if ((idx >> 11) == CPS - 1)
            out4[(TOTAL + NB) / 4 + nc4] = last;        // new_x[T-1]
        if (idx < NB) {
            float* outf = (float*)out4;
            outf[TOTAL + idx] = (float)(cached_len[idx] + TT);
        }
    }
}

extern "C" void kernel_launch(void* const* d_in, const int* in_sizes, int n_in,
                              void* d_out, int out_size) {
    const float4* x4         = (const float4*)d_in[0];   // (T, N, C)
    const int*    cached_len = (const int*)d_in[1];      // (N,)
    const float4* avg4       = (const float4*)d_in[2];   // (N, C)
    float4* out4 = (float4*)d_out;

    int extras = (out_size >= TOTAL + NB + NC) ? 1 : 0;

    kA<<<SEG_BLOCKS + RCP_BLOCKS, 256>>>(x4, cached_len);
    for (int s = 0; s < NSEG; s++) {
        kscan<<<NC4 / 256, 256>>>(cached_len, avg4, s);
        int nblk = (s < NSEG - 1) ? 2 * SEG_BLOCKS : SEG_BLOCKS;
        kC<<<nblk, 256>>>(x4, cached_len, out4, s, extras);
    }
}